// round 1
// baseline (speedup 1.0000x reference)
#include <cuda_runtime.h>

#define NMAX 100000
#define EMAX 640000
#define CH   128
#define CH4  32
#define BK   32

// ---------------- scratch (static device globals; no allocation) ----------------
__device__ float g_deg[NMAX];
__device__ float g_D[NMAX];
__device__ int   g_cnt[NMAX];
__device__ int   g_rowptr[NMAX + 1];
__device__ int   g_cursor[NMAX];
__device__ int   g_ecol[EMAX];
__device__ float g_eval[EMAX];
__device__ float g_Y[(size_t)NMAX * CH];
__device__ int   g_blksums[128];

// ---------------- small prep kernels ----------------
__global__ void k_zero(int N) {
    int i = blockIdx.x * blockDim.x + threadIdx.x;
    if (i < N) { g_deg[i] = 0.f; g_cnt[i] = 0; }
}

__global__ void k_deg(const int* __restrict__ row, const float* __restrict__ vals, int E) {
    int e = blockIdx.x * blockDim.x + threadIdx.x;
    if (e < E) {
        int r = row[e];
        atomicAdd(&g_deg[r], vals[e]);
        atomicAdd(&g_cnt[r], 1);
    }
}

// per-1024-chunk inclusive scan of g_cnt; local inclusive -> g_rowptr[i+1];
// chunk totals -> g_blksums. Also fuses D = rsqrt(deg+1).
__global__ void k_scan1(int N) {
    __shared__ int s[1024];
    int t = threadIdx.x;
    int i = blockIdx.x * 1024 + t;
    int v = (i < N) ? g_cnt[i] : 0;
    s[t] = v;
    __syncthreads();
    for (int off = 1; off < 1024; off <<= 1) {
        int x = (t >= off) ? s[t - off] : 0;
        __syncthreads();
        s[t] += x;
        __syncthreads();
    }
    if (i < N) {
        g_rowptr[i + 1] = s[t];
        g_D[i] = rsqrtf(g_deg[i] + 1.0f);
    }
    if (t == 1023) g_blksums[blockIdx.x] = s[t];
}

__global__ void k_scan2(int nb) {
    if (threadIdx.x == 0 && blockIdx.x == 0) {
        int acc = 0;
        for (int b = 0; b < nb; b++) { int v = g_blksums[b]; g_blksums[b] = acc; acc += v; }
    }
}

__global__ void k_scan3(int N) {
    int i = blockIdx.x * blockDim.x + threadIdx.x;
    if (i < N) {
        int incl = g_rowptr[i + 1] + g_blksums[i >> 10];
        g_rowptr[i + 1] = incl;
        g_cursor[i] = incl - g_cnt[i];      // exclusive start
        if (i == 0) g_rowptr[0] = 0;
    }
}

__global__ void k_fill(const int* __restrict__ row, const int* __restrict__ col,
                       const float* __restrict__ vals, int E) {
    int e = blockIdx.x * blockDim.x + threadIdx.x;
    if (e < E) {
        int p = atomicAdd(&g_cursor[row[e]], 1);
        g_ecol[p] = col[e];
        g_eval[p] = vals[e];
    }
}

// ---------------- GEMM: Y = D[:,None] * (X @ W) ----------------
// Block: 256 threads, computes 64 rows x 128 cols, K tiled by 32.
__global__ __launch_bounds__(256, 2) void k_gemm(const float* __restrict__ X,
                                                 const float* __restrict__ W, int N) {
    __shared__ __align__(16) float Ws[BK * CH];   // [k][out]  16 KB
    __shared__ __align__(16) float Xs[BK * 68];   // [k][row(64), pad 68]  8.5 KB

    int tid = threadIdx.x;
    int row0 = blockIdx.x * 64;
    int rg = tid >> 4;   // 0..15  (4 rows each)
    int cg = tid & 15;   // 0..15  (8 cols each)

    float acc[4][8];
#pragma unroll
    for (int i = 0; i < 4; i++)
#pragma unroll
        for (int j = 0; j < 8; j++) acc[i][j] = 0.f;

    const float4* X4 = (const float4*)X;
    const float4* W4 = (const float4*)W;

    for (int kt = 0; kt < CH; kt += BK) {
        // load W tile: 32 x 128 floats = 1024 float4
#pragma unroll
        for (int it = 0; it < 4; it++) {
            int idx = tid + it * 256;          // 0..1023
            int kk = idx >> 5;                  // 0..31
            int q  = idx & 31;                  // float4 within row
            ((float4*)Ws)[idx] = W4[(size_t)(kt + kk) * CH4 + q];
        }
        // load X tile transposed: 64 rows x 8 float4 -> Xs[k][row]
#pragma unroll
        for (int it = 0; it < 2; it++) {
            int idx = tid + it * 256;          // 0..511
            int r = idx >> 3;                   // 0..63
            int q = idx & 7;                    // float4 within BK
            int gr = row0 + r;
            float4 v = (gr < N) ? X4[(size_t)gr * CH4 + (kt >> 2) + q]
                                : make_float4(0.f, 0.f, 0.f, 0.f);
            int kk = q * 4;
            Xs[(kk + 0) * 68 + r] = v.x;
            Xs[(kk + 1) * 68 + r] = v.y;
            Xs[(kk + 2) * 68 + r] = v.z;
            Xs[(kk + 3) * 68 + r] = v.w;
        }
        __syncthreads();

#pragma unroll
        for (int k = 0; k < BK; k++) {
            float4 av = *(const float4*)&Xs[k * 68 + rg * 4];
            float4 b0 = *(const float4*)&Ws[k * CH + cg * 8];
            float4 b1 = *(const float4*)&Ws[k * CH + cg * 8 + 4];
            float a_[4] = {av.x, av.y, av.z, av.w};
            float b_[8] = {b0.x, b0.y, b0.z, b0.w, b1.x, b1.y, b1.z, b1.w};
#pragma unroll
            for (int i = 0; i < 4; i++)
#pragma unroll
                for (int j = 0; j < 8; j++)
                    acc[i][j] = fmaf(a_[i], b_[j], acc[i][j]);
        }
        __syncthreads();
    }

    // epilogue: Y[gr] = D[gr] * acc
#pragma unroll
    for (int i = 0; i < 4; i++) {
        int gr = row0 + rg * 4 + i;
        if (gr < N) {
            float d = g_D[gr];
            float4 o0 = make_float4(d * acc[i][0], d * acc[i][1], d * acc[i][2], d * acc[i][3]);
            float4 o1 = make_float4(d * acc[i][4], d * acc[i][5], d * acc[i][6], d * acc[i][7]);
            float4* Yp = (float4*)&g_Y[(size_t)gr * CH + cg * 8];
            Yp[0] = o0;
            Yp[1] = o1;
        }
    }
}

// ---------------- aggregation: out = D * (A @ Y) + bias ----------------
// One warp per row; atomic-free (CSR built above). Each lane owns a float4 (4 ch).
__global__ void k_agg(const float* __restrict__ bias, float* __restrict__ out, int N) {
    int gw = (blockIdx.x * blockDim.x + threadIdx.x) >> 5;
    int lane = threadIdx.x & 31;
    if (gw >= N) return;
    int s = g_rowptr[gw], e = g_rowptr[gw + 1];
    float4 acc = make_float4(0.f, 0.f, 0.f, 0.f);
    const float4* Y4 = (const float4*)g_Y;
    for (int i = s; i < e; i++) {
        int   c = __ldg(&g_ecol[i]);
        float v = __ldg(&g_eval[i]);
        float4 y = Y4[(size_t)c * CH4 + lane];
        acc.x = fmaf(v, y.x, acc.x);
        acc.y = fmaf(v, y.y, acc.y);
        acc.z = fmaf(v, y.z, acc.z);
        acc.w = fmaf(v, y.w, acc.w);
    }
    float d = g_D[gw];
    float4 b = ((const float4*)bias)[lane];
    float4 o = make_float4(fmaf(d, acc.x, b.x), fmaf(d, acc.y, b.y),
                           fmaf(d, acc.z, b.z), fmaf(d, acc.w, b.w));
    ((float4*)out)[(size_t)gw * CH4 + lane] = o;
}

// ---------------- launch ----------------
extern "C" void kernel_launch(void* const* d_in, const int* in_sizes, int n_in,
                              void* d_out, int out_size) {
    const int*   row  = (const int*)d_in[0];
    const int*   col  = (const int*)d_in[1];
    const float* vals = (const float*)d_in[2];
    const float* X    = (const float*)d_in[3];
    const float* W    = (const float*)d_in[4];
    const float* bias = (const float*)d_in[5];
    int E = in_sizes[0];
    int N = in_sizes[3] / CH;
    float* out = (float*)d_out;

    int nb_scan = (N + 1023) / 1024;

    k_zero <<<(N + 255) / 256, 256>>>(N);
    k_deg  <<<(E + 255) / 256, 256>>>(row, vals, E);
    k_scan1<<<nb_scan, 1024>>>(N);
    k_scan2<<<1, 32>>>(nb_scan);
    k_scan3<<<(N + 255) / 256, 256>>>(N);
    k_fill <<<(E + 255) / 256, 256>>>(row, col, vals, E);
    k_gemm <<<(N + 63) / 64, 256>>>(X, W, N);
    k_agg  <<<(N * 32 + 255) / 256, 256>>>(bias, out, N);
}

// round 2
// speedup vs baseline: 1.8881x; 1.8881x over previous
#include <cuda_runtime.h>

#define NMAX 100000
#define EMAX 640000
#define CH   128
#define CH4  32
#define MBLK 128
#define BKC  32
#define LDX  36
#define LDW  136

// ---------------- scratch (static device globals; no allocation) ----------------
__device__ float g_deg[NMAX];
__device__ float g_D[NMAX];
__device__ int   g_cnt[NMAX];
__device__ int   g_rowptr[NMAX + 1];
__device__ int   g_cursor[NMAX];
__device__ int   g_ecol[EMAX];
__device__ float g_eval[EMAX];
__device__ float g_Y[(size_t)NMAX * CH];
__device__ int   g_blksums[128];

// ---------------- small prep kernels ----------------
__global__ void k_zero(int N) {
    int i = blockIdx.x * blockDim.x + threadIdx.x;
    if (i < N) { g_deg[i] = 0.f; g_cnt[i] = 0; }
}

__global__ void k_deg(const int* __restrict__ row, const float* __restrict__ vals, int E) {
    int e = blockIdx.x * blockDim.x + threadIdx.x;
    if (e < E) {
        int r = row[e];
        atomicAdd(&g_deg[r], vals[e]);
        atomicAdd(&g_cnt[r], 1);
    }
}

// per-1024-chunk inclusive scan of g_cnt -> g_rowptr[i+1]; chunk totals -> g_blksums.
// Also fuses D = rsqrt(deg+1).
__global__ void k_scan1(int N) {
    __shared__ int s[1024];
    int t = threadIdx.x;
    int i = blockIdx.x * 1024 + t;
    int v = (i < N) ? g_cnt[i] : 0;
    s[t] = v;
    __syncthreads();
    for (int off = 1; off < 1024; off <<= 1) {
        int x = (t >= off) ? s[t - off] : 0;
        __syncthreads();
        s[t] += x;
        __syncthreads();
    }
    if (i < N) {
        g_rowptr[i + 1] = s[t];
        g_D[i] = rsqrtf(g_deg[i] + 1.0f);
    }
    if (t == 1023) g_blksums[blockIdx.x] = s[t];
}

// single-block parallel exclusive scan of block sums (nb <= 128)
__global__ void k_scan2(int nb) {
    __shared__ int sh[4];
    int t = threadIdx.x;                     // 128 threads
    int v = (t < nb) ? g_blksums[t] : 0;
    int x = v;
    int lane = t & 31;
#pragma unroll
    for (int o = 1; o < 32; o <<= 1) {
        int y = __shfl_up_sync(0xFFFFFFFFu, x, o);
        if (lane >= o) x += y;
    }
    if (lane == 31) sh[t >> 5] = x;
    __syncthreads();
    if (t < 32) {
        int wv = (t < 4) ? sh[t] : 0;
#pragma unroll
        for (int o = 1; o < 4; o <<= 1) {
            int y = __shfl_up_sync(0xFFFFFFFFu, wv, o);
            if (lane >= o) wv += y;
        }
        if (t < 4) sh[t] = wv;
    }
    __syncthreads();
    int base = (t >= 32) ? sh[(t >> 5) - 1] : 0;
    if (t < nb) g_blksums[t] = base + x - v;   // exclusive
}

__global__ void k_scan3(int N) {
    int i = blockIdx.x * blockDim.x + threadIdx.x;
    if (i < N) {
        int incl = g_rowptr[i + 1] + g_blksums[i >> 10];
        g_rowptr[i + 1] = incl;
        g_cursor[i] = incl - g_cnt[i];      // exclusive start
        if (i == 0) g_rowptr[0] = 0;
    }
}

__global__ void k_fill(const int* __restrict__ row, const int* __restrict__ col,
                       const float* __restrict__ vals, int E) {
    int e = blockIdx.x * blockDim.x + threadIdx.x;
    if (e < E) {
        int p = atomicAdd(&g_cursor[row[e]], 1);
        g_ecol[p] = col[e];
        g_eval[p] = vals[e];
    }
}

// ---------------- GEMM (tf32 tensor cores): Y = D[:,None] * (X @ W) ----------------
__device__ __forceinline__ unsigned f2tf32(float x) {
    unsigned r;
    asm("cvt.rna.tf32.f32 %0, %1;" : "=r"(r) : "f"(x));
    return r;
}

__global__ __launch_bounds__(256, 2) void k_gemm_tc(const float* __restrict__ X,
                                                    const float* __restrict__ W, int N) {
    __shared__ __align__(16) unsigned Xs[MBLK * LDX];   // 128 x 32 tf32, ld=36 (conflict-free)
    __shared__ __align__(16) unsigned Ws[BKC * LDW];    // 32 x 128 tf32, ld=136 (conflict-free)

    int tid = threadIdx.x;
    int lane = tid & 31;
    int w = tid >> 5;
    int g = lane >> 2;         // groupID 0..7
    int t = lane & 3;          // thread in group 0..3
    int warpM = w >> 1;        // 0..3
    int warpN = w & 1;         // 0..1
    int mbase = warpM * 32;
    int nbase = warpN * 64;
    int row0 = blockIdx.x * MBLK;

    float c[2][8][4];
#pragma unroll
    for (int mi = 0; mi < 2; mi++)
#pragma unroll
        for (int ni = 0; ni < 8; ni++)
#pragma unroll
            for (int q = 0; q < 4; q++) c[mi][ni][q] = 0.f;

    const float4* X4 = (const float4*)X;
    const float4* W4 = (const float4*)W;

    for (int kt = 0; kt < CH; kt += BKC) {
        // stage X tile: 128 x 32 floats = 1024 float4
#pragma unroll
        for (int it = 0; it < 4; it++) {
            int idx = tid + it * 256;
            int r = idx >> 3, q = idx & 7;
            int gr = row0 + r;
            float4 v = (gr < N) ? X4[(size_t)gr * CH4 + (kt >> 2) + q]
                                : make_float4(0.f, 0.f, 0.f, 0.f);
            unsigned* p = &Xs[r * LDX + q * 4];
            p[0] = f2tf32(v.x); p[1] = f2tf32(v.y); p[2] = f2tf32(v.z); p[3] = f2tf32(v.w);
        }
        // stage W tile: 32 x 128 floats = 1024 float4
#pragma unroll
        for (int it = 0; it < 4; it++) {
            int idx = tid + it * 256;
            int k = idx >> 5, q = idx & 31;
            float4 v = W4[(size_t)(kt + k) * CH4 + q];
            unsigned* p = &Ws[k * LDW + q * 4];
            p[0] = f2tf32(v.x); p[1] = f2tf32(v.y); p[2] = f2tf32(v.z); p[3] = f2tf32(v.w);
        }
        __syncthreads();

#pragma unroll
        for (int kk = 0; kk < BKC; kk += 8) {
            unsigned a[2][4];
#pragma unroll
            for (int mi = 0; mi < 2; mi++) {
                int r = mbase + mi * 16;
                a[mi][0] = Xs[(r + g) * LDX + kk + t];
                a[mi][1] = Xs[(r + g + 8) * LDX + kk + t];
                a[mi][2] = Xs[(r + g) * LDX + kk + t + 4];
                a[mi][3] = Xs[(r + g + 8) * LDX + kk + t + 4];
            }
#pragma unroll
            for (int ni = 0; ni < 8; ni++) {
                int cn = nbase + ni * 8 + g;
                unsigned b0 = Ws[(kk + t) * LDW + cn];
                unsigned b1 = Ws[(kk + t + 4) * LDW + cn];
#pragma unroll
                for (int mi = 0; mi < 2; mi++) {
                    asm volatile(
                        "mma.sync.aligned.m16n8k8.row.col.f32.tf32.tf32.f32 "
                        "{%0,%1,%2,%3}, {%4,%5,%6,%7}, {%8,%9}, {%0,%1,%2,%3};"
                        : "+f"(c[mi][ni][0]), "+f"(c[mi][ni][1]),
                          "+f"(c[mi][ni][2]), "+f"(c[mi][ni][3])
                        : "r"(a[mi][0]), "r"(a[mi][1]), "r"(a[mi][2]), "r"(a[mi][3]),
                          "r"(b0), "r"(b1));
                }
            }
        }
        __syncthreads();
    }

    // epilogue: Y[r] = D[r] * acc
#pragma unroll
    for (int mi = 0; mi < 2; mi++) {
        int r0 = row0 + mbase + mi * 16 + g;
        int r1 = r0 + 8;
        float d0 = (r0 < N) ? g_D[r0] : 0.f;
        float d1 = (r1 < N) ? g_D[r1] : 0.f;
#pragma unroll
        for (int ni = 0; ni < 8; ni++) {
            int cn = nbase + ni * 8 + 2 * t;
            if (r0 < N) {
                float2 o = make_float2(d0 * c[mi][ni][0], d0 * c[mi][ni][1]);
                *(float2*)&g_Y[(size_t)r0 * CH + cn] = o;
            }
            if (r1 < N) {
                float2 o = make_float2(d1 * c[mi][ni][2], d1 * c[mi][ni][3]);
                *(float2*)&g_Y[(size_t)r1 * CH + cn] = o;
            }
        }
    }
}

// ---------------- aggregation: out = D * (A @ Y) + bias ----------------
__global__ void k_agg(const float* __restrict__ bias, float* __restrict__ out, int N) {
    int gw = (blockIdx.x * blockDim.x + threadIdx.x) >> 5;
    int lane = threadIdx.x & 31;
    if (gw >= N) return;
    int s = g_rowptr[gw], e = g_rowptr[gw + 1];
    float4 acc = make_float4(0.f, 0.f, 0.f, 0.f);
    const float4* Y4 = (const float4*)g_Y;
    for (int i = s; i < e; i++) {
        int   cix = __ldg(&g_ecol[i]);
        float v   = __ldg(&g_eval[i]);
        float4 y = Y4[(size_t)cix * CH4 + lane];
        acc.x = fmaf(v, y.x, acc.x);
        acc.y = fmaf(v, y.y, acc.y);
        acc.z = fmaf(v, y.z, acc.z);
        acc.w = fmaf(v, y.w, acc.w);
    }
    float d = g_D[gw];
    float4 b = ((const float4*)bias)[lane];
    float4 o = make_float4(fmaf(d, acc.x, b.x), fmaf(d, acc.y, b.y),
                           fmaf(d, acc.z, b.z), fmaf(d, acc.w, b.w));
    ((float4*)out)[(size_t)gw * CH4 + lane] = o;
}

// ---------------- launch ----------------
extern "C" void kernel_launch(void* const* d_in, const int* in_sizes, int n_in,
                              void* d_out, int out_size) {
    const int*   row  = (const int*)d_in[0];
    const int*   col  = (const int*)d_in[1];
    const float* vals = (const float*)d_in[2];
    const float* X    = (const float*)d_in[3];
    const float* W    = (const float*)d_in[4];
    const float* bias = (const float*)d_in[5];
    int E = in_sizes[0];
    int N = in_sizes[3] / CH;
    float* out = (float*)d_out;

    int nb_scan = (N + 1023) / 1024;

    k_zero   <<<(N + 255) / 256, 256>>>(N);
    k_deg    <<<(E + 255) / 256, 256>>>(row, vals, E);
    k_scan1  <<<nb_scan, 1024>>>(N);
    k_scan2  <<<1, 128>>>(nb_scan);
    k_scan3  <<<(N + 255) / 256, 256>>>(N);
    k_fill   <<<(E + 255) / 256, 256>>>(row, col, vals, E);
    k_gemm_tc<<<(N + MBLK - 1) / MBLK, 256>>>(X, W, N);
    k_agg    <<<(N * 32 + 255) / 256, 256>>>(bias, out, N);
}

// round 3
// speedup vs baseline: 2.0599x; 1.0910x over previous
#include <cuda_runtime.h>

#define NMAX 100000
#define EMAX 640000
#define CH   128
#define CH4  32
#define MBLK 128
#define BKC  32
#define LDX  36
#define LDW  136

// ---------------- scratch (static device globals; no allocation) ----------------
__device__ float g_deg[NMAX];
__device__ float g_D[NMAX];
__device__ int   g_cnt[NMAX];
__device__ int   g_rowptr[NMAX + 1];
__device__ int   g_cursor[NMAX];
__device__ int   g_ecol[EMAX];
__device__ float g_eval[EMAX];
__device__ float g_Y[(size_t)NMAX * CH];
__device__ int   g_blksums[128];

// ---------------- small prep kernels ----------------
__global__ void k_zero(int N) {
    int i = blockIdx.x * blockDim.x + threadIdx.x;
    if (i < N) { g_deg[i] = 0.f; g_cnt[i] = 0; }
}

__global__ void k_deg(const int* __restrict__ row, const float* __restrict__ vals, int E) {
    int e = blockIdx.x * blockDim.x + threadIdx.x;
    if (e < E) {
        int r = row[e];
        atomicAdd(&g_deg[r], vals[e]);
        atomicAdd(&g_cnt[r], 1);
    }
}

// per-1024-chunk inclusive scan of g_cnt -> g_rowptr[i+1]; chunk totals -> g_blksums.
// Also fuses D = rsqrt(deg+1).
__global__ void k_scan1(int N) {
    __shared__ int ws[32];
    int t = threadIdx.x;
    int lane = t & 31, wid = t >> 5;
    int i = blockIdx.x * 1024 + t;
    int v = (i < N) ? g_cnt[i] : 0;
    int x = v;
#pragma unroll
    for (int o = 1; o < 32; o <<= 1) {
        int y = __shfl_up_sync(0xFFFFFFFFu, x, o);
        if (lane >= o) x += y;
    }
    if (lane == 31) ws[wid] = x;
    __syncthreads();
    if (t < 32) {
        int wv = ws[t];
#pragma unroll
        for (int o = 1; o < 32; o <<= 1) {
            int y = __shfl_up_sync(0xFFFFFFFFu, wv, o);
            if (lane >= o) wv += y;
        }
        ws[t] = wv;
    }
    __syncthreads();
    int base = (wid > 0) ? ws[wid - 1] : 0;
    int incl = base + x;
    if (i < N) {
        g_rowptr[i + 1] = incl;
        g_D[i] = rsqrtf(g_deg[i] + 1.0f);
    }
    if (t == 1023) g_blksums[blockIdx.x] = incl;
}

// single-block parallel exclusive scan of block sums (nb <= 128)
__global__ void k_scan2(int nb) {
    __shared__ int sh[4];
    int t = threadIdx.x;                     // 128 threads
    int v = (t < nb) ? g_blksums[t] : 0;
    int x = v;
    int lane = t & 31;
#pragma unroll
    for (int o = 1; o < 32; o <<= 1) {
        int y = __shfl_up_sync(0xFFFFFFFFu, x, o);
        if (lane >= o) x += y;
    }
    if (lane == 31) sh[t >> 5] = x;
    __syncthreads();
    if (t < 32) {
        int wv = (t < 4) ? sh[t] : 0;
#pragma unroll
        for (int o = 1; o < 4; o <<= 1) {
            int y = __shfl_up_sync(0xFFFFFFFFu, wv, o);
            if (lane >= o) wv += y;
        }
        if (t < 4) sh[t] = wv;
    }
    __syncthreads();
    int base = (t >= 32) ? sh[(t >> 5) - 1] : 0;
    if (t < nb) g_blksums[t] = base + x - v;   // exclusive
}

__global__ void k_scan3(int N) {
    int i = blockIdx.x * blockDim.x + threadIdx.x;
    if (i < N) {
        int incl = g_rowptr[i + 1] + g_blksums[i >> 10];
        g_rowptr[i + 1] = incl;
        g_cursor[i] = incl - g_cnt[i];      // exclusive start
        if (i == 0) g_rowptr[0] = 0;
    }
}

// fill CSR; fold D[col] into edge value so the GEMM never needs D
__global__ void k_fill(const int* __restrict__ row, const int* __restrict__ col,
                       const float* __restrict__ vals, int E) {
    int e = blockIdx.x * blockDim.x + threadIdx.x;
    if (e < E) {
        int c = col[e];
        int p = atomicAdd(&g_cursor[row[e]], 1);
        g_ecol[p] = c;
        g_eval[p] = vals[e] * __ldg(&g_D[c]);
    }
}

// ---------------- GEMM (tf32 tensor cores): Y = X @ W (no D — folded into eval) ----------------
__device__ __forceinline__ unsigned f2tf32(float x) {
    unsigned r;
    asm("cvt.rna.tf32.f32 %0, %1;" : "=r"(r) : "f"(x));
    return r;
}

__global__ __launch_bounds__(256, 2) void k_gemm_tc(const float* __restrict__ X,
                                                    const float* __restrict__ W, int N) {
    __shared__ __align__(16) unsigned Xs[MBLK * LDX];   // 128 x 32 tf32, ld=36 (conflict-free)
    __shared__ __align__(16) unsigned Ws[BKC * LDW];    // 32 x 128 tf32, ld=136 (conflict-free)

    int tid = threadIdx.x;
    int lane = tid & 31;
    int w = tid >> 5;
    int g = lane >> 2;         // groupID 0..7
    int t = lane & 3;          // thread in group 0..3
    int warpM = w >> 1;        // 0..3
    int warpN = w & 1;         // 0..1
    int mbase = warpM * 32;
    int nbase = warpN * 64;
    int row0 = blockIdx.x * MBLK;

    float c[2][8][4];
#pragma unroll
    for (int mi = 0; mi < 2; mi++)
#pragma unroll
        for (int ni = 0; ni < 8; ni++)
#pragma unroll
            for (int q = 0; q < 4; q++) c[mi][ni][q] = 0.f;

    const float4* X4 = (const float4*)X;
    const float4* W4 = (const float4*)W;

    for (int kt = 0; kt < CH; kt += BKC) {
        // stage X tile: 128 x 32 floats = 1024 float4
#pragma unroll
        for (int it = 0; it < 4; it++) {
            int idx = tid + it * 256;
            int r = idx >> 3, q = idx & 7;
            int gr = row0 + r;
            float4 v = (gr < N) ? X4[(size_t)gr * CH4 + (kt >> 2) + q]
                                : make_float4(0.f, 0.f, 0.f, 0.f);
            unsigned* p = &Xs[r * LDX + q * 4];
            p[0] = f2tf32(v.x); p[1] = f2tf32(v.y); p[2] = f2tf32(v.z); p[3] = f2tf32(v.w);
        }
        // stage W tile: 32 x 128 floats = 1024 float4
#pragma unroll
        for (int it = 0; it < 4; it++) {
            int idx = tid + it * 256;
            int k = idx >> 5, q = idx & 31;
            float4 v = W4[(size_t)(kt + k) * CH4 + q];
            unsigned* p = &Ws[k * LDW + q * 4];
            p[0] = f2tf32(v.x); p[1] = f2tf32(v.y); p[2] = f2tf32(v.z); p[3] = f2tf32(v.w);
        }
        __syncthreads();

#pragma unroll
        for (int kk = 0; kk < BKC; kk += 8) {
            unsigned a[2][4];
#pragma unroll
            for (int mi = 0; mi < 2; mi++) {
                int r = mbase + mi * 16;
                a[mi][0] = Xs[(r + g) * LDX + kk + t];
                a[mi][1] = Xs[(r + g + 8) * LDX + kk + t];
                a[mi][2] = Xs[(r + g) * LDX + kk + t + 4];
                a[mi][3] = Xs[(r + g + 8) * LDX + kk + t + 4];
            }
#pragma unroll
            for (int ni = 0; ni < 8; ni++) {
                int cn = nbase + ni * 8 + g;
                unsigned b0 = Ws[(kk + t) * LDW + cn];
                unsigned b1 = Ws[(kk + t + 4) * LDW + cn];
#pragma unroll
                for (int mi = 0; mi < 2; mi++) {
                    asm volatile(
                        "mma.sync.aligned.m16n8k8.row.col.f32.tf32.tf32.f32 "
                        "{%0,%1,%2,%3}, {%4,%5,%6,%7}, {%8,%9}, {%0,%1,%2,%3};"
                        : "+f"(c[mi][ni][0]), "+f"(c[mi][ni][1]),
                          "+f"(c[mi][ni][2]), "+f"(c[mi][ni][3])
                        : "r"(a[mi][0]), "r"(a[mi][1]), "r"(a[mi][2]), "r"(a[mi][3]),
                          "r"(b0), "r"(b1));
                }
            }
        }
        __syncthreads();
    }

    // epilogue: raw Y (no D scaling)
#pragma unroll
    for (int mi = 0; mi < 2; mi++) {
        int r0 = row0 + mbase + mi * 16 + g;
        int r1 = r0 + 8;
#pragma unroll
        for (int ni = 0; ni < 8; ni++) {
            int cn = nbase + ni * 8 + 2 * t;
            if (r0 < N) {
                float2 o = make_float2(c[mi][ni][0], c[mi][ni][1]);
                *(float2*)&g_Y[(size_t)r0 * CH + cn] = o;
            }
            if (r1 < N) {
                float2 o = make_float2(c[mi][ni][2], c[mi][ni][3]);
                *(float2*)&g_Y[(size_t)r1 * CH + cn] = o;
            }
        }
    }
}

// ---------------- aggregation: out = D * (A' @ Y) + bias  (A' has D[col] folded in) ----------------
__global__ void k_agg(const float* __restrict__ bias, float* __restrict__ out, int N) {
    int gw = (blockIdx.x * blockDim.x + threadIdx.x) >> 5;
    int lane = threadIdx.x & 31;
    if (gw >= N) return;
    int s = g_rowptr[gw], e = g_rowptr[gw + 1];
    float4 acc = make_float4(0.f, 0.f, 0.f, 0.f);
    const float4* Y4 = (const float4*)g_Y;
    for (int i = s; i < e; i++) {
        int   cix = __ldg(&g_ecol[i]);
        float v   = __ldg(&g_eval[i]);
        float4 y = Y4[(size_t)cix * CH4 + lane];
        acc.x = fmaf(v, y.x, acc.x);
        acc.y = fmaf(v, y.y, acc.y);
        acc.z = fmaf(v, y.z, acc.z);
        acc.w = fmaf(v, y.w, acc.w);
    }
    float d = g_D[gw];
    float4 b = ((const float4*)bias)[lane];
    float4 o = make_float4(fmaf(d, acc.x, b.x), fmaf(d, acc.y, b.y),
                           fmaf(d, acc.z, b.z), fmaf(d, acc.w, b.w));
    ((float4*)out)[(size_t)gw * CH4 + lane] = o;
}

// ---------------- launch: fork/join — GEMM overlaps the CSR build ----------------
extern "C" void kernel_launch(void* const* d_in, const int* in_sizes, int n_in,
                              void* d_out, int out_size) {
    const int*   row  = (const int*)d_in[0];
    const int*   col  = (const int*)d_in[1];
    const float* vals = (const float*)d_in[2];
    const float* X    = (const float*)d_in[3];
    const float* W    = (const float*)d_in[4];
    const float* bias = (const float*)d_in[5];
    int E = in_sizes[0];
    int N = in_sizes[3] / CH;
    float* out = (float*)d_out;

    static cudaStream_t s2 = nullptr;
    static cudaEvent_t evFork = nullptr, evJoin = nullptr;
    if (s2 == nullptr) {
        cudaStreamCreateWithFlags(&s2, cudaStreamNonBlocking);
        cudaEventCreateWithFlags(&evFork, cudaEventDisableTiming);
        cudaEventCreateWithFlags(&evJoin, cudaEventDisableTiming);
    }

    int nb_scan = (N + 1023) / 1024;
    bool overlap = (s2 != nullptr && evFork != nullptr && evJoin != nullptr);
    cudaStream_t sp = overlap ? s2 : (cudaStream_t)0;   // prep stream

    if (overlap) {
        cudaEventRecord(evFork, 0);
        cudaStreamWaitEvent(s2, evFork, 0);
    }

    // main stream: GEMM (independent of the prep chain now)
    k_gemm_tc<<<(N + MBLK - 1) / MBLK, 256, 0, 0>>>(X, W, N);

    // prep stream: CSR build + D
    k_zero <<<(N + 255) / 256, 256, 0, sp>>>(N);
    k_deg  <<<(E + 255) / 256, 256, 0, sp>>>(row, vals, E);
    k_scan1<<<nb_scan, 1024, 0, sp>>>(N);
    k_scan2<<<1, 128, 0, sp>>>(nb_scan);
    k_scan3<<<(N + 255) / 256, 256, 0, sp>>>(N);
    k_fill <<<(E + 255) / 256, 256, 0, sp>>>(row, col, vals, E);

    if (overlap) {
        cudaEventRecord(evJoin, s2);
        cudaStreamWaitEvent(0, evJoin, 0);
    }

    // join: aggregation needs Y, CSR, D
    k_agg<<<(N * 32 + 255) / 256, 256, 0, 0>>>(bias, out, N);
}

// round 4
// speedup vs baseline: 2.1661x; 1.0516x over previous
#include <cuda_runtime.h>
#include <cuda_fp16.h>

#define NMAX 100000
#define EMAX 640000
#define CH   128
#define CH4  32
#define MBLK 128
#define BKC  32
#define LDX  36
#define LDW  136

// ---------------- scratch (static device globals; no allocation) ----------------
__device__ float g_deg[NMAX];
__device__ float g_D[NMAX];
__device__ int   g_cnt[NMAX];
__device__ int   g_rowptr[NMAX + 1];
__device__ int   g_cursor[NMAX];
__device__ int   g_ecol[EMAX];
__device__ float g_eval[EMAX];
__device__ __half g_Yh[(size_t)NMAX * CH];
__device__ int   g_blksums[128];
__device__ int   g_blkoff[128];
__device__ int   g_ticket;

// ---------------- small prep kernels ----------------
__global__ void k_zero(int N) {
    int i = blockIdx.x * blockDim.x + threadIdx.x;
    if (i < N) { g_deg[i] = 0.f; g_cnt[i] = 0; }
    if (i == 0) g_ticket = 0;
}

__global__ void k_deg(const int* __restrict__ row, const float* __restrict__ vals, int E) {
    int e = blockIdx.x * blockDim.x + threadIdx.x;
    if (e < E) {
        int r = row[e];
        atomicAdd(&g_deg[r], vals[e]);
        atomicAdd(&g_cnt[r], 1);
    }
}

// fused scan1+scan2: per-1024-chunk inclusive scan of g_cnt -> g_rowptr[i+1];
// fuses D = rsqrt(deg+1); LAST block to finish scans the block sums (no spinning).
__global__ void k_scanA(int N, int nb) {
    __shared__ int ws[32];
    __shared__ int isLast;
    int t = threadIdx.x;
    int lane = t & 31, wid = t >> 5;
    int b = blockIdx.x;
    int i = b * 1024 + t;
    int v = (i < N) ? g_cnt[i] : 0;
    int x = v;
#pragma unroll
    for (int o = 1; o < 32; o <<= 1) {
        int y = __shfl_up_sync(0xFFFFFFFFu, x, o);
        if (lane >= o) x += y;
    }
    if (lane == 31) ws[wid] = x;
    __syncthreads();
    if (t < 32) {
        int wv = ws[t];
#pragma unroll
        for (int o = 1; o < 32; o <<= 1) {
            int y = __shfl_up_sync(0xFFFFFFFFu, wv, o);
            if (lane >= o) wv += y;
        }
        ws[t] = wv;
    }
    __syncthreads();
    int base = (wid > 0) ? ws[wid - 1] : 0;
    int incl = base + x;
    if (i < N) {
        g_rowptr[i + 1] = incl;
        g_D[i] = rsqrtf(g_deg[i] + 1.0f);
    }
    if (t == 1023) g_blksums[b] = incl;

    __threadfence();
    if (t == 0) isLast = (atomicAdd(&g_ticket, 1) == nb - 1) ? 1 : 0;
    __syncthreads();
    if (isLast && t < 32) {
        volatile int* bs = g_blksums;
        int run = 0;
        for (int c0 = 0; c0 < nb; c0 += 32) {
            int idx = c0 + lane;
            int val = (idx < nb) ? bs[idx] : 0;
            int xx = val;
#pragma unroll
            for (int o = 1; o < 32; o <<= 1) {
                int y = __shfl_up_sync(0xFFFFFFFFu, xx, o);
                if (lane >= o) xx += y;
            }
            if (idx < nb) g_blkoff[idx] = run + xx - val;  // exclusive
            run += __shfl_sync(0xFFFFFFFFu, xx, 31);
        }
        __threadfence();
    }
}

__global__ void k_scan3(int N) {
    int i = blockIdx.x * blockDim.x + threadIdx.x;
    if (i < N) {
        int incl = g_rowptr[i + 1] + g_blkoff[i >> 10];
        g_rowptr[i + 1] = incl;
        g_cursor[i] = incl - g_cnt[i];      // exclusive start
        if (i == 0) g_rowptr[0] = 0;
    }
}

// fill CSR; fold D[col] into edge value so the GEMM never needs D
__global__ void k_fill(const int* __restrict__ row, const int* __restrict__ col,
                       const float* __restrict__ vals, int E) {
    int e = blockIdx.x * blockDim.x + threadIdx.x;
    if (e < E) {
        int c = col[e];
        int p = atomicAdd(&g_cursor[row[e]], 1);
        g_ecol[p] = c;
        g_eval[p] = vals[e] * __ldg(&g_D[c]);
    }
}

// ---------------- GEMM (tf32 tensor cores): Yh = fp16(X @ W) ----------------
__device__ __forceinline__ unsigned f2tf32(float x) {
    unsigned r;
    asm("cvt.rna.tf32.f32 %0, %1;" : "=r"(r) : "f"(x));
    return r;
}

__global__ __launch_bounds__(256, 2) void k_gemm_tc(const float* __restrict__ X,
                                                    const float* __restrict__ W, int N) {
    __shared__ __align__(16) unsigned Xs[MBLK * LDX];   // 128 x 32 tf32, ld=36 (conflict-free)
    __shared__ __align__(16) unsigned Ws[BKC * LDW];    // 32 x 128 tf32, ld=136 (conflict-free)

    int tid = threadIdx.x;
    int lane = tid & 31;
    int w = tid >> 5;
    int g = lane >> 2;         // groupID 0..7
    int t = lane & 3;          // thread in group 0..3
    int warpM = w >> 1;        // 0..3
    int warpN = w & 1;         // 0..1
    int mbase = warpM * 32;
    int nbase = warpN * 64;
    int row0 = blockIdx.x * MBLK;

    float c[2][8][4];
#pragma unroll
    for (int mi = 0; mi < 2; mi++)
#pragma unroll
        for (int ni = 0; ni < 8; ni++)
#pragma unroll
            for (int q = 0; q < 4; q++) c[mi][ni][q] = 0.f;

    const float4* X4 = (const float4*)X;
    const float4* W4 = (const float4*)W;

    for (int kt = 0; kt < CH; kt += BKC) {
#pragma unroll
        for (int it = 0; it < 4; it++) {
            int idx = tid + it * 256;
            int r = idx >> 3, q = idx & 7;
            int gr = row0 + r;
            float4 v = (gr < N) ? X4[(size_t)gr * CH4 + (kt >> 2) + q]
                                : make_float4(0.f, 0.f, 0.f, 0.f);
            unsigned* p = &Xs[r * LDX + q * 4];
            p[0] = f2tf32(v.x); p[1] = f2tf32(v.y); p[2] = f2tf32(v.z); p[3] = f2tf32(v.w);
        }
#pragma unroll
        for (int it = 0; it < 4; it++) {
            int idx = tid + it * 256;
            int k = idx >> 5, q = idx & 31;
            float4 v = W4[(size_t)(kt + k) * CH4 + q];
            unsigned* p = &Ws[k * LDW + q * 4];
            p[0] = f2tf32(v.x); p[1] = f2tf32(v.y); p[2] = f2tf32(v.z); p[3] = f2tf32(v.w);
        }
        __syncthreads();

#pragma unroll
        for (int kk = 0; kk < BKC; kk += 8) {
            unsigned a[2][4];
#pragma unroll
            for (int mi = 0; mi < 2; mi++) {
                int r = mbase + mi * 16;
                a[mi][0] = Xs[(r + g) * LDX + kk + t];
                a[mi][1] = Xs[(r + g + 8) * LDX + kk + t];
                a[mi][2] = Xs[(r + g) * LDX + kk + t + 4];
                a[mi][3] = Xs[(r + g + 8) * LDX + kk + t + 4];
            }
#pragma unroll
            for (int ni = 0; ni < 8; ni++) {
                int cn = nbase + ni * 8 + g;
                unsigned b0 = Ws[(kk + t) * LDW + cn];
                unsigned b1 = Ws[(kk + t + 4) * LDW + cn];
#pragma unroll
                for (int mi = 0; mi < 2; mi++) {
                    asm volatile(
                        "mma.sync.aligned.m16n8k8.row.col.f32.tf32.tf32.f32 "
                        "{%0,%1,%2,%3}, {%4,%5,%6,%7}, {%8,%9}, {%0,%1,%2,%3};"
                        : "+f"(c[mi][ni][0]), "+f"(c[mi][ni][1]),
                          "+f"(c[mi][ni][2]), "+f"(c[mi][ni][3])
                        : "r"(a[mi][0]), "r"(a[mi][1]), "r"(a[mi][2]), "r"(a[mi][3]),
                          "r"(b0), "r"(b1));
                }
            }
        }
        __syncthreads();
    }

    // epilogue: Yh = fp16(acc)
#pragma unroll
    for (int mi = 0; mi < 2; mi++) {
        int r0 = row0 + mbase + mi * 16 + g;
        int r1 = r0 + 8;
#pragma unroll
        for (int ni = 0; ni < 8; ni++) {
            int cn = nbase + ni * 8 + 2 * t;
            if (r0 < N)
                *(__half2*)&g_Yh[(size_t)r0 * CH + cn] = __floats2half2_rn(c[mi][ni][0], c[mi][ni][1]);
            if (r1 < N)
                *(__half2*)&g_Yh[(size_t)r1 * CH + cn] = __floats2half2_rn(c[mi][ni][2], c[mi][ni][3]);
        }
    }
}

// ---------------- aggregation: out = D * (A' @ Yh) + bias ----------------
__global__ void k_agg(const float* __restrict__ bias, float* __restrict__ out, int N) {
    int gw = (blockIdx.x * blockDim.x + threadIdx.x) >> 5;
    int lane = threadIdx.x & 31;
    if (gw >= N) return;
    int s = g_rowptr[gw], e = g_rowptr[gw + 1];
    float4 acc = make_float4(0.f, 0.f, 0.f, 0.f);
    const uint2* Y2 = (const uint2*)g_Yh;

    int i = s;
    for (; i + 1 < e; i += 2) {
        int   c0 = __ldg(&g_ecol[i]);
        int   c1 = __ldg(&g_ecol[i + 1]);
        float v0 = __ldg(&g_eval[i]);
        float v1 = __ldg(&g_eval[i + 1]);
        uint2 u0 = __ldg(&Y2[(size_t)c0 * 32 + lane]);
        uint2 u1 = __ldg(&Y2[(size_t)c1 * 32 + lane]);
        float2 a0 = __half22float2(*(__half2*)&u0.x);
        float2 b0 = __half22float2(*(__half2*)&u0.y);
        float2 a1 = __half22float2(*(__half2*)&u1.x);
        float2 b1 = __half22float2(*(__half2*)&u1.y);
        acc.x = fmaf(v0, a0.x, fmaf(v1, a1.x, acc.x));
        acc.y = fmaf(v0, a0.y, fmaf(v1, a1.y, acc.y));
        acc.z = fmaf(v0, b0.x, fmaf(v1, b1.x, acc.z));
        acc.w = fmaf(v0, b0.y, fmaf(v1, b1.y, acc.w));
    }
    if (i < e) {
        int   c0 = __ldg(&g_ecol[i]);
        float v0 = __ldg(&g_eval[i]);
        uint2 u0 = __ldg(&Y2[(size_t)c0 * 32 + lane]);
        float2 a0 = __half22float2(*(__half2*)&u0.x);
        float2 b0 = __half22float2(*(__half2*)&u0.y);
        acc.x = fmaf(v0, a0.x, acc.x);
        acc.y = fmaf(v0, a0.y, acc.y);
        acc.z = fmaf(v0, b0.x, acc.z);
        acc.w = fmaf(v0, b0.y, acc.w);
    }

    float d = g_D[gw];
    float4 b = ((const float4*)bias)[lane];
    float4 o = make_float4(fmaf(d, acc.x, b.x), fmaf(d, acc.y, b.y),
                           fmaf(d, acc.z, b.z), fmaf(d, acc.w, b.w));
    ((float4*)out)[(size_t)gw * CH4 + lane] = o;
}

// ---------------- launch: fork/join — GEMM overlaps the CSR build ----------------
extern "C" void kernel_launch(void* const* d_in, const int* in_sizes, int n_in,
                              void* d_out, int out_size) {
    const int*   row  = (const int*)d_in[0];
    const int*   col  = (const int*)d_in[1];
    const float* vals = (const float*)d_in[2];
    const float* X    = (const float*)d_in[3];
    const float* W    = (const float*)d_in[4];
    const float* bias = (const float*)d_in[5];
    int E = in_sizes[0];
    int N = in_sizes[3] / CH;
    float* out = (float*)d_out;

    static cudaStream_t s2 = nullptr;
    static cudaEvent_t evFork = nullptr, evJoin = nullptr;
    if (s2 == nullptr) {
        cudaStreamCreateWithFlags(&s2, cudaStreamNonBlocking);
        cudaEventCreateWithFlags(&evFork, cudaEventDisableTiming);
        cudaEventCreateWithFlags(&evJoin, cudaEventDisableTiming);
    }

    int nb_scan = (N + 1023) / 1024;
    bool overlap = (s2 != nullptr && evFork != nullptr && evJoin != nullptr);
    cudaStream_t sp = overlap ? s2 : (cudaStream_t)0;   // prep stream

    if (overlap) {
        cudaEventRecord(evFork, 0);
        cudaStreamWaitEvent(s2, evFork, 0);
    }

    // main stream: GEMM (independent of the prep chain)
    k_gemm_tc<<<(N + MBLK - 1) / MBLK, 256, 0, 0>>>(X, W, N);

    // prep stream: CSR build + D
    k_zero <<<(N + 255) / 256, 256, 0, sp>>>(N);
    k_deg  <<<(E + 255) / 256, 256, 0, sp>>>(row, vals, E);
    k_scanA<<<nb_scan, 1024, 0, sp>>>(N, nb_scan);
    k_scan3<<<(N + 255) / 256, 256, 0, sp>>>(N);
    k_fill <<<(E + 255) / 256, 256, 0, sp>>>(row, col, vals, E);

    if (overlap) {
        cudaEventRecord(evJoin, s2);
        cudaStreamWaitEvent(0, evJoin, 0);
    }

    // join: aggregation needs Yh, CSR, D
    k_agg<<<(N * 32 + 255) / 256, 256, 0, 0>>>(bias, out, N);
}

// round 5
// speedup vs baseline: 2.2094x; 1.0200x over previous
#include <cuda_runtime.h>
#include <cuda_fp16.h>

#define NMAX 100000
#define EMAX 640000
#define CH   128
#define CH4  32
#define MBLK 128
#define BKC  32
#define LDX  36
#define LDW  136

// ---------------- scratch (static device globals; no allocation) ----------------
__device__ float g_deg[NMAX];
__device__ float g_D[NMAX];
__device__ int   g_cnt[NMAX];
__device__ int   g_rowptr[NMAX + 1];
__device__ int   g_cursor[NMAX];
__device__ int2  g_edge[EMAX];           // (col, val-as-int), D[col] folded into val
__device__ __half g_Yh[(size_t)NMAX * CH];
__device__ int   g_blksums[128];
__device__ int   g_blkoff[128];
__device__ int   g_ticket;

// ---------------- prep kernels ----------------
// degree + count accumulation (2 edges per thread, vector loads)
__global__ void k_deg(const int* __restrict__ row, const float* __restrict__ vals, int E) {
    int i = (blockIdx.x * blockDim.x + threadIdx.x) * 2;
    if (i + 1 < E) {
        int2   r2 = *(const int2*)&row[i];
        float2 v2 = *(const float2*)&vals[i];
        atomicAdd(&g_deg[r2.x], v2.x);
        atomicAdd(&g_cnt[r2.x], 1);
        atomicAdd(&g_deg[r2.y], v2.y);
        atomicAdd(&g_cnt[r2.y], 1);
    } else if (i < E) {
        int r = row[i];
        atomicAdd(&g_deg[r], vals[i]);
        atomicAdd(&g_cnt[r], 1);
    }
}

// fused scan: 256 threads x 4 elems = 1024 per block. Local inclusive -> rowptr[i+1];
// D = rsqrt(deg+1). Last block (ticket) exclusive-scans block sums into g_blkoff.
__global__ void k_scanA(int N, int nb) {
    __shared__ int ws[8];
    __shared__ int isLast;
    int t = threadIdx.x;
    int lane = t & 31, wid = t >> 5;
    int b = blockIdx.x;
    int i0 = b * 1024 + t * 4;

    int4 c4;
    if (i0 + 3 < N) c4 = *(const int4*)&g_cnt[i0];
    else {
        c4.x = (i0 + 0 < N) ? g_cnt[i0 + 0] : 0;
        c4.y = (i0 + 1 < N) ? g_cnt[i0 + 1] : 0;
        c4.z = (i0 + 2 < N) ? g_cnt[i0 + 2] : 0;
        c4.w = (i0 + 3 < N) ? g_cnt[i0 + 3] : 0;
    }
    int p0 = c4.x, p1 = p0 + c4.y, p2 = p1 + c4.z, p3 = p2 + c4.w;
    int x = p3;
#pragma unroll
    for (int o = 1; o < 32; o <<= 1) {
        int y = __shfl_up_sync(0xFFFFFFFFu, x, o);
        if (lane >= o) x += y;
    }
    if (lane == 31) ws[wid] = x;
    __syncthreads();
    if (t < 32) {
        int wv = (t < 8) ? ws[t] : 0;
#pragma unroll
        for (int o = 1; o < 8; o <<= 1) {
            int y = __shfl_up_sync(0xFFFFFFFFu, wv, o);
            if (lane >= o) wv += y;
        }
        if (t < 8) ws[t] = wv;
    }
    __syncthreads();
    int texcl = ((wid > 0) ? ws[wid - 1] : 0) + x - p3;   // exclusive before this thread
    if (i0 + 0 < N) g_rowptr[i0 + 1] = texcl + p0;
    if (i0 + 1 < N) g_rowptr[i0 + 2] = texcl + p1;
    if (i0 + 2 < N) g_rowptr[i0 + 3] = texcl + p2;
    if (i0 + 3 < N) g_rowptr[i0 + 4] = texcl + p3;

    // D = rsqrt(deg + 1)
    if (i0 + 3 < N) {
        float4 dg = *(const float4*)&g_deg[i0];
        float4 dd = make_float4(rsqrtf(dg.x + 1.f), rsqrtf(dg.y + 1.f),
                                rsqrtf(dg.z + 1.f), rsqrtf(dg.w + 1.f));
        *(float4*)&g_D[i0] = dd;
    } else {
#pragma unroll
        for (int k = 0; k < 4; k++)
            if (i0 + k < N) g_D[i0 + k] = rsqrtf(g_deg[i0 + k] + 1.f);
    }

    if (t == 0) {
        g_blksums[b] = ws[7];          // block total
        __threadfence();
        isLast = (atomicAdd(&g_ticket, 1) == nb - 1) ? 1 : 0;
    }
    __syncthreads();
    if (isLast && t < 32) {
        volatile int* bs = g_blksums;
        int run = 0;
        for (int c0 = 0; c0 < nb; c0 += 32) {
            int idx = c0 + lane;
            int val = (idx < nb) ? bs[idx] : 0;
            int xx = val;
#pragma unroll
            for (int o = 1; o < 32; o <<= 1) {
                int y = __shfl_up_sync(0xFFFFFFFFu, xx, o);
                if (lane >= o) xx += y;
            }
            if (idx < nb) g_blkoff[idx] = run + xx - val;   // exclusive
            run += __shfl_sync(0xFFFFFFFFu, xx, 31);
        }
    }
}

__global__ void k_scan3(int N) {
    int i = blockIdx.x * blockDim.x + threadIdx.x;
    if (i < N) {
        int incl = g_rowptr[i + 1] + g_blkoff[i >> 10];
        g_rowptr[i + 1] = incl;
        g_cursor[i] = incl - g_cnt[i];
        if (i == 0) g_rowptr[0] = 0;
    }
}

// fill CSR with packed (col, val*D[col]) edges; 2 edges per thread
__global__ void k_fill(const int* __restrict__ row, const int* __restrict__ col,
                       const float* __restrict__ vals, int E) {
    int i = (blockIdx.x * blockDim.x + threadIdx.x) * 2;
    if (i + 1 < E) {
        int2   r2 = *(const int2*)&row[i];
        int2   c2 = *(const int2*)&col[i];
        float2 v2 = *(const float2*)&vals[i];
        float  e0 = v2.x * __ldg(&g_D[c2.x]);
        float  e1 = v2.y * __ldg(&g_D[c2.y]);
        int p0 = atomicAdd(&g_cursor[r2.x], 1);
        g_edge[p0] = make_int2(c2.x, __float_as_int(e0));
        int p1 = atomicAdd(&g_cursor[r2.y], 1);
        g_edge[p1] = make_int2(c2.y, __float_as_int(e1));
    } else if (i < E) {
        int c = col[i];
        float ev = vals[i] * __ldg(&g_D[c]);
        int p = atomicAdd(&g_cursor[row[i]], 1);
        g_edge[p] = make_int2(c, __float_as_int(ev));
    }
}

// tail reset (runs concurrently with k_agg on the other stream)
__global__ void k_reset(int N) {
    int i = blockIdx.x * blockDim.x + threadIdx.x;
    int i4 = i * 4;
    if (i4 + 3 < N) {
        *(float4*)&g_deg[i4] = make_float4(0.f, 0.f, 0.f, 0.f);
        *(int4*)&g_cnt[i4] = make_int4(0, 0, 0, 0);
    } else {
        for (int k = 0; k < 4; k++)
            if (i4 + k < N) { g_deg[i4 + k] = 0.f; g_cnt[i4 + k] = 0; }
    }
    if (i == 0) g_ticket = 0;
}

// ---------------- GEMM (tf32 tensor cores): Yh = fp16(X @ W) ----------------
__device__ __forceinline__ unsigned f2tf32(float x) {
    unsigned r;
    asm("cvt.rna.tf32.f32 %0, %1;" : "=r"(r) : "f"(x));
    return r;
}

__global__ __launch_bounds__(256, 2) void k_gemm_tc(const float* __restrict__ X,
                                                    const float* __restrict__ W, int N) {
    __shared__ __align__(16) unsigned Xs[MBLK * LDX];
    __shared__ __align__(16) unsigned Ws[BKC * LDW];

    int tid = threadIdx.x;
    int lane = tid & 31;
    int w = tid >> 5;
    int g = lane >> 2;
    int t = lane & 3;
    int warpM = w >> 1;
    int warpN = w & 1;
    int mbase = warpM * 32;
    int nbase = warpN * 64;
    int row0 = blockIdx.x * MBLK;

    float c[2][8][4];
#pragma unroll
    for (int mi = 0; mi < 2; mi++)
#pragma unroll
        for (int ni = 0; ni < 8; ni++)
#pragma unroll
            for (int q = 0; q < 4; q++) c[mi][ni][q] = 0.f;

    const float4* X4 = (const float4*)X;
    const float4* W4 = (const float4*)W;

    for (int kt = 0; kt < CH; kt += BKC) {
#pragma unroll
        for (int it = 0; it < 4; it++) {
            int idx = tid + it * 256;
            int r = idx >> 3, q = idx & 7;
            int gr = row0 + r;
            float4 v = (gr < N) ? X4[(size_t)gr * CH4 + (kt >> 2) + q]
                                : make_float4(0.f, 0.f, 0.f, 0.f);
            unsigned* p = &Xs[r * LDX + q * 4];
            p[0] = f2tf32(v.x); p[1] = f2tf32(v.y); p[2] = f2tf32(v.z); p[3] = f2tf32(v.w);
        }
#pragma unroll
        for (int it = 0; it < 4; it++) {
            int idx = tid + it * 256;
            int k = idx >> 5, q = idx & 31;
            float4 v = W4[(size_t)(kt + k) * CH4 + q];
            unsigned* p = &Ws[k * LDW + q * 4];
            p[0] = f2tf32(v.x); p[1] = f2tf32(v.y); p[2] = f2tf32(v.z); p[3] = f2tf32(v.w);
        }
        __syncthreads();

#pragma unroll
        for (int kk = 0; kk < BKC; kk += 8) {
            unsigned a[2][4];
#pragma unroll
            for (int mi = 0; mi < 2; mi++) {
                int r = mbase + mi * 16;
                a[mi][0] = Xs[(r + g) * LDX + kk + t];
                a[mi][1] = Xs[(r + g + 8) * LDX + kk + t];
                a[mi][2] = Xs[(r + g) * LDX + kk + t + 4];
                a[mi][3] = Xs[(r + g + 8) * LDX + kk + t + 4];
            }
#pragma unroll
            for (int ni = 0; ni < 8; ni++) {
                int cn = nbase + ni * 8 + g;
                unsigned b0 = Ws[(kk + t) * LDW + cn];
                unsigned b1 = Ws[(kk + t + 4) * LDW + cn];
#pragma unroll
                for (int mi = 0; mi < 2; mi++) {
                    asm volatile(
                        "mma.sync.aligned.m16n8k8.row.col.f32.tf32.tf32.f32 "
                        "{%0,%1,%2,%3}, {%4,%5,%6,%7}, {%8,%9}, {%0,%1,%2,%3};"
                        : "+f"(c[mi][ni][0]), "+f"(c[mi][ni][1]),
                          "+f"(c[mi][ni][2]), "+f"(c[mi][ni][3])
                        : "r"(a[mi][0]), "r"(a[mi][1]), "r"(a[mi][2]), "r"(a[mi][3]),
                          "r"(b0), "r"(b1));
                }
            }
        }
        __syncthreads();
    }

#pragma unroll
    for (int mi = 0; mi < 2; mi++) {
        int r0 = row0 + mbase + mi * 16 + g;
        int r1 = r0 + 8;
#pragma unroll
        for (int ni = 0; ni < 8; ni++) {
            int cn = nbase + ni * 8 + 2 * t;
            if (r0 < N)
                *(__half2*)&g_Yh[(size_t)r0 * CH + cn] = __floats2half2_rn(c[mi][ni][0], c[mi][ni][1]);
            if (r1 < N)
                *(__half2*)&g_Yh[(size_t)r1 * CH + cn] = __floats2half2_rn(c[mi][ni][2], c[mi][ni][3]);
        }
    }
}

// ---------------- aggregation: out = D * (A' @ Yh) + bias ----------------
// One warp per row; lanes 0-15 handle edge i, lanes 16-31 edge i+1.
// Each lane owns 8 channels via one uint4 (16B of fp16) per edge.
__global__ void k_agg(const float* __restrict__ bias, float* __restrict__ out, int N) {
    int gw = (blockIdx.x * blockDim.x + threadIdx.x) >> 5;
    int lane = threadIdx.x & 31;
    if (gw >= N) return;
    int g2 = lane >> 4;
    int sub = lane & 15;
    int s = g_rowptr[gw], e = g_rowptr[gw + 1];

    float acc[8];
#pragma unroll
    for (int j = 0; j < 8; j++) acc[j] = 0.f;

    const uint4* Y4 = (const uint4*)g_Yh;    // 16 uint4 per 128-ch row
    for (int i = s; i < e; i += 2) {
        int idx = i + g2;
        if (idx < e) {
            int2 ed = __ldg(&g_edge[idx]);
            float v = __int_as_float(ed.y);
            uint4 u = __ldg(&Y4[(size_t)ed.x * 16 + sub]);
            float2 f0 = __half22float2(*(__half2*)&u.x);
            float2 f1 = __half22float2(*(__half2*)&u.y);
            float2 f2 = __half22float2(*(__half2*)&u.z);
            float2 f3 = __half22float2(*(__half2*)&u.w);
            acc[0] = fmaf(v, f0.x, acc[0]);
            acc[1] = fmaf(v, f0.y, acc[1]);
            acc[2] = fmaf(v, f1.x, acc[2]);
            acc[3] = fmaf(v, f1.y, acc[3]);
            acc[4] = fmaf(v, f2.x, acc[4]);
            acc[5] = fmaf(v, f2.y, acc[5]);
            acc[6] = fmaf(v, f3.x, acc[6]);
            acc[7] = fmaf(v, f3.y, acc[7]);
        }
    }
#pragma unroll
    for (int j = 0; j < 8; j++)
        acc[j] += __shfl_xor_sync(0xFFFFFFFFu, acc[j], 16);

    if (g2 == 0) {
        float d = g_D[gw];
        float4 b0 = __ldg(&((const float4*)bias)[sub * 2]);
        float4 b1 = __ldg(&((const float4*)bias)[sub * 2 + 1]);
        float4 o0 = make_float4(fmaf(d, acc[0], b0.x), fmaf(d, acc[1], b0.y),
                                fmaf(d, acc[2], b0.z), fmaf(d, acc[3], b0.w));
        float4 o1 = make_float4(fmaf(d, acc[4], b1.x), fmaf(d, acc[5], b1.y),
                                fmaf(d, acc[6], b1.z), fmaf(d, acc[7], b1.w));
        float4* op = (float4*)&out[(size_t)gw * CH + sub * 8];
        op[0] = o0;
        op[1] = o1;
    }
}

// ---------------- launch: fork/join — GEMM overlaps CSR build; reset overlaps agg ----------------
extern "C" void kernel_launch(void* const* d_in, const int* in_sizes, int n_in,
                              void* d_out, int out_size) {
    const int*   row  = (const int*)d_in[0];
    const int*   col  = (const int*)d_in[1];
    const float* vals = (const float*)d_in[2];
    const float* X    = (const float*)d_in[3];
    const float* W    = (const float*)d_in[4];
    const float* bias = (const float*)d_in[5];
    int E = in_sizes[0];
    int N = in_sizes[3] / CH;
    float* out = (float*)d_out;

    static cudaStream_t s2 = nullptr;
    static cudaEvent_t evFork = nullptr, evJoin = nullptr, evJoin2 = nullptr;
    if (s2 == nullptr) {
        cudaStreamCreateWithFlags(&s2, cudaStreamNonBlocking);
        cudaEventCreateWithFlags(&evFork, cudaEventDisableTiming);
        cudaEventCreateWithFlags(&evJoin, cudaEventDisableTiming);
        cudaEventCreateWithFlags(&evJoin2, cudaEventDisableTiming);
    }

    int nb_scan = (N + 1023) / 1024;
    int half_e  = (E + 1) / 2;

    cudaEventRecord(evFork, 0);
    cudaStreamWaitEvent(s2, evFork, 0);

    // main stream: GEMM (independent of the prep chain)
    k_gemm_tc<<<(N + MBLK - 1) / MBLK, 256, 0, 0>>>(X, W, N);

    // prep stream: CSR build + D   (globals are zero-init on first run; k_reset restores)
    k_deg  <<<(half_e + 255) / 256, 256, 0, s2>>>(row, vals, E);
    k_scanA<<<nb_scan, 256, 0, s2>>>(N, nb_scan);
    k_scan3<<<(N + 255) / 256, 256, 0, s2>>>(N);
    k_fill <<<(half_e + 255) / 256, 256, 0, s2>>>(row, col, vals, E);
    cudaEventRecord(evJoin, s2);

    // tail reset on s2 — overlaps agg on stream 0
    k_reset<<<(N / 4 + 255) / 256, 256, 0, s2>>>(N);
    cudaEventRecord(evJoin2, s2);

    cudaStreamWaitEvent(0, evJoin, 0);
    k_agg<<<(N * 32 + 255) / 256, 256, 0, 0>>>(bias, out, N);
    cudaStreamWaitEvent(0, evJoin2, 0);
}